// round 3
// baseline (speedup 1.0000x reference)
#include <cuda_runtime.h>
#include <cstdint>

#define BATCH 256
#define N 64
#define DIM 768
#define CHUNK 64
#define NCHUNK 12
#define DP 68                      // smem D pitch in gram kernel
#define CP 66                      // smem D pitch in cluster kernel
#define BIGV 1e9f
#define KINF 0xFFFFFFFFFFFFFFFFull

typedef unsigned long long u64;
typedef unsigned int u32;

// global scratch (device globals: allocation-free)
__device__ float g_D[BATCH * N * N];        // 4 MB distance matrices (diag=BIG)
__device__ u64   g_rowkey[BATCH * N];       // per-row min keys
__device__ int   g_merges[BATCH];
__device__ float g_partials[BATCH * 4];     // [simN, disN, simC, errC]

__device__ __forceinline__ u64 u64min(u64 a, u64 b) { return a < b ? a : b; }
__device__ __forceinline__ u64 packkey(float v, int flat) {
    return (((u64)__float_as_uint(v)) << 32) | (unsigned)flat;
}

union F4U { float4 f; u64 u[2]; };

// ---------------------------------------------------------------------------
// K0: per-batch merge counts (also pads launch count so ncu -s 5 hits gram)
// ---------------------------------------------------------------------------
__global__ __launch_bounds__(256) void prep_kernel(const int* __restrict__ labels)
{
    int b = threadIdx.x;
    int mask = 0;
    #pragma unroll 8
    for (int j = 0; j < N; j++) mask |= 1 << labels[b * N + j];
    g_merges[b] = N - __popc(mask);
}

// ---------------------------------------------------------------------------
// K1: Gram + distances + rowkeys + sim/dis partials.  grid 256 x 128 thr.
// ---------------------------------------------------------------------------
union SmemU {
    float ST[2][CHUNK][64];   // 32 KB double-buffered scaled tiles (k-major, swizzled)
    float D[N][DP];           // 17 KB distance matrix (used after GEMM)
};

__global__ __launch_bounds__(128) void gram_kernel(
    const float* __restrict__ q,
    const float* __restrict__ p,
    const int* __restrict__ labels_g)
{
    __shared__ SmemU u;
    __shared__ float sqv[N];
    __shared__ int   lab_in[N];
    __shared__ float wred[4][4];

    const int tid = threadIdx.x;
    const int b   = blockIdx.x;
    const float* pb = p + (size_t)b * N * DIM;
    const float* qb = q + (size_t)b * DIM;

    if (tid < N) lab_in[tid] = labels_g[b * N + tid];

    const int ti = tid >> 3, tj = tid & 7;
    const int i0 = ti * 4, j0 = tj * 8;
    const int kvq  = (tid & 15) * 4;    // constant k-column offset for this thread
    const int kqb  = kvq >> 2;          // k-block index for swizzle
    const int prow = tid >> 4;          // base row (+8e)

    u64 acc[4][4];
    #pragma unroll
    for (int r = 0; r < 4; r++)
        #pragma unroll
        for (int cp = 0; cp < 4; cp++) acc[r][cp] = 0ull;

    // prologue: prefetch chunk 0
    float4 pv[8];
    float4 qv = *reinterpret_cast<const float4*>(qb + kvq);
    #pragma unroll
    for (int e = 0; e < 8; e++)
        pv[e] = *reinterpret_cast<const float4*>(pb + (prow + 8 * e) * DIM + kvq);

    for (int ch = 0; ch < NCHUNK; ch++) {
        const int bsel = ch & 1;
        // store scaled tile into ST[bsel] (k-major + XOR swizzle)
        #pragma unroll
        for (int e = 0; e < 8; e++) {
            int row = prow + 8 * e;
            int col = (((row >> 2) ^ kqb) << 2) + (row & 3);
            u.ST[bsel][kvq + 0][col] = pv[e].x * qv.x;
            u.ST[bsel][kvq + 1][col] = pv[e].y * qv.y;
            u.ST[bsel][kvq + 2][col] = pv[e].z * qv.z;
            u.ST[bsel][kvq + 3][col] = pv[e].w * qv.w;
        }
        // prefetch next chunk (hidden behind this chunk's compute)
        if (ch + 1 < NCHUNK) {
            qv = *reinterpret_cast<const float4*>(qb + (ch + 1) * CHUNK + kvq);
            #pragma unroll
            for (int e = 0; e < 8; e++)
                pv[e] = *reinterpret_cast<const float4*>(
                            pb + (prow + 8 * e) * DIM + (ch + 1) * CHUNK + kvq);
        }
        __syncthreads();
        // compute on ST[bsel]
        #pragma unroll
        for (int k4 = 0; k4 < 16; k4++) {
            const int avc  = ((ti ^ k4) << 2);
            const int bvc0 = (((2 * tj)     ^ k4) << 2);
            const int bvc1 = (((2 * tj + 1) ^ k4) << 2);
            #pragma unroll
            for (int t = 0; t < 4; t++) {
                const int kk = k4 * 4 + t;
                float4 av = *reinterpret_cast<const float4*>(&u.ST[bsel][kk][avc]);
                F4U B0, B1;
                B0.f = *reinterpret_cast<const float4*>(&u.ST[bsel][kk][bvc0]);
                B1.f = *reinterpret_cast<const float4*>(&u.ST[bsel][kk][bvc1]);
                u64 a0, a1, a2, a3;
                asm("mov.b64 %0, {%1,%1};" : "=l"(a0) : "f"(av.x));
                asm("mov.b64 %0, {%1,%1};" : "=l"(a1) : "f"(av.y));
                asm("mov.b64 %0, {%1,%1};" : "=l"(a2) : "f"(av.z));
                asm("mov.b64 %0, {%1,%1};" : "=l"(a3) : "f"(av.w));
                #pragma unroll
                for (int cp = 0; cp < 4; cp++) {
                    u64 bq = (cp < 2) ? B0.u[cp] : B1.u[cp - 2];
                    asm("fma.rn.f32x2 %0, %1, %2, %0;" : "+l"(acc[0][cp]) : "l"(a0), "l"(bq));
                    asm("fma.rn.f32x2 %0, %1, %2, %0;" : "+l"(acc[1][cp]) : "l"(a1), "l"(bq));
                    asm("fma.rn.f32x2 %0, %1, %2, %0;" : "+l"(acc[2][cp]) : "l"(a2), "l"(bq));
                    asm("fma.rn.f32x2 %0, %1, %2, %0;" : "+l"(acc[3][cp]) : "l"(a3), "l"(bq));
                }
            }
        }
    }

    // unpack accumulators
    float af[4][8];
    #pragma unroll
    for (int r = 0; r < 4; r++)
        #pragma unroll
        for (int cp = 0; cp < 4; cp++) {
            float lo, hi;
            asm("mov.b64 {%0,%1}, %2;" : "=f"(lo), "=f"(hi) : "l"(acc[r][cp]));
            af[r][2 * cp] = lo; af[r][2 * cp + 1] = hi;
        }

    __syncthreads();   // all computes done: ST region now reusable as D

    #pragma unroll
    for (int r = 0; r < 4; r++) {
        int i = i0 + r;
        if (i >= j0 && i < j0 + 8) sqv[i] = af[r][i - j0];
    }
    __syncthreads();

    float simN = 0.f, disN = 0.f, simC = 0.f;
    #pragma unroll
    for (int r = 0; r < 4; r++) {
        int i = i0 + r;
        int li = lab_in[i];
        #pragma unroll
        for (int c = 0; c < 8; c++) {
            int j = j0 + c;
            float d2 = sqv[i] + sqv[j] - 2.f * af[r][c];
            float dist = (d2 > 0.f) ? sqrtf(d2) : 0.f;
            u.D[i][j] = dist;
            if (li == lab_in[j]) { simN += dist; simC += 1.f; }
            else                 { disN += dist; }
        }
    }
    __syncthreads();
    if (tid < N) u.D[tid][tid] = BIGV;
    __syncthreads();

    // rowkeys: 2 threads/row, 32 cols each
    {
        int row = tid >> 1, part = tid & 1;
        u64 key = KINF;
        #pragma unroll
        for (int f = 0; f < 8; f++) {
            int c = part * 32 + f * 4;
            float4 v = *reinterpret_cast<const float4*>(&u.D[row][c]);
            key = u64min(key, packkey(v.x, row * 64 + c + 0));
            key = u64min(key, packkey(v.y, row * 64 + c + 1));
            key = u64min(key, packkey(v.z, row * 64 + c + 2));
            key = u64min(key, packkey(v.w, row * 64 + c + 3));
        }
        key = u64min(key, __shfl_down_sync(0xFFFFFFFFu, key, 1));
        if (part == 0) g_rowkey[b * 64 + row] = key;
    }

    // D -> global (diag already BIG)
    {
        float* gdst = g_D + (size_t)b * (N * N);
        #pragma unroll
        for (int e = 0; e < 8; e++) {
            int idx = tid + e * 128;
            int row = idx >> 4, c4 = (idx & 15) * 4;
            *reinterpret_cast<float4*>(gdst + row * 64 + c4) =
                *reinterpret_cast<const float4*>(&u.D[row][c4]);
        }
    }

    // block reduce partials
    float v0 = simN, v1 = disN, v2 = simC;
    #pragma unroll
    for (int o = 16; o > 0; o >>= 1) {
        v0 += __shfl_down_sync(0xFFFFFFFFu, v0, o);
        v1 += __shfl_down_sync(0xFFFFFFFFu, v1, o);
        v2 += __shfl_down_sync(0xFFFFFFFFu, v2, o);
    }
    if ((tid & 31) == 0) {
        int w = tid >> 5;
        wred[w][0] = v0; wred[w][1] = v1; wred[w][2] = v2;
    }
    __syncthreads();
    if (tid == 0) {
        float a0 = 0.f, a1 = 0.f, a2 = 0.f;
        #pragma unroll
        for (int w = 0; w < 4; w++) { a0 += wred[w][0]; a1 += wred[w][1]; a2 += wred[w][2]; }
        g_partials[b * 4 + 0] = a0;
        g_partials[b * 4 + 1] = a1;
        g_partials[b * 4 + 2] = a2;
    }
}

// ---------------------------------------------------------------------------
// K2: single-linkage clustering + error count.  grid 256 x 32 thr (1 warp).
// ---------------------------------------------------------------------------
__global__ __launch_bounds__(32) void cluster_kernel(const int* __restrict__ labels_g)
{
    __shared__ float Dsm[N * CP];
    __shared__ int   lab_in[N];
    __shared__ int   lab_cl[N];

    const int lane = threadIdx.x;
    const int b    = blockIdx.x;
    const int c0 = 2 * lane, c1 = c0 + 1;
    const float* gd = g_D + (size_t)b * (N * N);

    // load D (4096 floats) into smem, pitch CP
    #pragma unroll
    for (int e = 0; e < 32; e++) {
        int idx4 = lane + e * 32;                 // float4 index 0..1023
        float4 v = *reinterpret_cast<const float4*>(gd + idx4 * 4);
        int row = idx4 >> 4, col = (idx4 & 15) * 4;
        float* dst = &Dsm[row * CP + col];
        dst[0] = v.x; dst[1] = v.y; dst[2] = v.z; dst[3] = v.w;
    }
    lab_in[c0] = labels_g[b * N + c0];
    lab_in[c1] = labels_g[b * N + c1];
    __syncwarp();

    const int merges = g_merges[b];
    u64 rk0 = g_rowkey[b * 64 + c0];
    u64 rk1 = g_rowkey[b * 64 + c1];
    u64 pend = KINF;
    u64 act = ~0ull;
    int aprev = -1;
    int lab0 = c0, lab1 = c1;

    for (int m = 0; m < merges; m++) {
        u64 cand = u64min(u64min(rk0, rk1), pend);
        // warp argmin of cand (two-phase u32 redux; tie-break = min flat)
        u32 chi = (u32)(cand >> 32);
        u32 h  = __reduce_min_sync(0xFFFFFFFFu, chi);
        u32 cl = (chi == h) ? (u32)cand : 0xFFFFFFFFu;
        u32 l  = __reduce_min_sync(0xFFFFFFFFu, cl);
        // warp min of pend (to materialize rowkey of previous merge's row a)
        u32 phi = (u32)(pend >> 32);
        u32 ph  = __reduce_min_sync(0xFFFFFFFFu, phi);
        u32 plo = (phi == ph) ? (u32)pend : 0xFFFFFFFFu;
        u32 pl  = __reduce_min_sync(0xFFFFFFFFu, plo);
        if (aprev >= 0 && lane == (aprev >> 1)) {
            u64 pr = (((u64)ph) << 32) | pl;
            if (aprev & 1) rk1 = pr; else rk0 = pr;
        }

        int flat = (int)l;
        int a = flat >> 6, bb = flat & 63;        // a < bb (symmetric keys -> min flat)

        act &= ~(1ull << bb);

        float m0 = fminf(Dsm[a * CP + c0], Dsm[bb * CP + c0]);
        float m1 = fminf(Dsm[a * CP + c1], Dsm[bb * CP + c1]);
        Dsm[a * CP + c0] = m0; Dsm[a * CP + c1] = m1;
        Dsm[c0 * CP + a] = m0; Dsm[c1 * CP + a] = m1;

        u64 k0 = (((act >> c0) & 1ull) && c0 != a) ? packkey(m0, a * 64 + c0) : KINF;
        u64 k1 = (((act >> c1) & 1ull) && c1 != a) ? packkey(m1, a * 64 + c1) : KINF;
        pend = u64min(k0, k1);
        aprev = a;

        if (c0 == a || c0 == bb) rk0 = KINF;
        else if ((act >> c0) & 1ull) {
            if ((int)(rk0 & 63ull) == bb) rk0 = (rk0 & ~63ull) | (unsigned)a;
            rk0 = u64min(rk0, packkey(m0, c0 * 64 + a));
        }
        if (c1 == a || c1 == bb) rk1 = KINF;
        else if ((act >> c1) & 1ull) {
            if ((int)(rk1 & 63ull) == bb) rk1 = (rk1 & ~63ull) | (unsigned)a;
            rk1 = u64min(rk1, packkey(m1, c1 * 64 + a));
        }

        if (lab0 == bb) lab0 = a;
        if (lab1 == bb) lab1 = a;
    }

    lab_cl[c0] = lab0;
    lab_cl[c1] = lab1;
    __syncwarp();

    // error count: both rows of this lane
    int err = 0;
    int li0 = lab_in[c0], li1 = lab_in[c1];
    #pragma unroll 16
    for (int j = 0; j < N; j++) {
        int lc = lab_cl[j], lj = lab_in[j];
        err += ((lab0 == lc) != (li0 == lj));
        err += ((lab1 == lc) != (li1 == lj));
    }
    int tot = __reduce_add_sync(0xFFFFFFFFu, (u32)err);
    if (lane == 0) g_partials[b * 4 + 3] = (float)tot;
}

// ---------------------------------------------------------------------------
// K3: finalize
// ---------------------------------------------------------------------------
__global__ __launch_bounds__(256) void finalize_kernel(float* __restrict__ out)
{
    __shared__ double sh[8][4];
    const int tid = threadIdx.x;
    double v0 = g_partials[tid * 4 + 0];
    double v1 = g_partials[tid * 4 + 1];
    double v2 = g_partials[tid * 4 + 2];
    double v3 = g_partials[tid * 4 + 3];
    #pragma unroll
    for (int o = 16; o > 0; o >>= 1) {
        v0 += __shfl_down_sync(0xFFFFFFFFu, v0, o);
        v1 += __shfl_down_sync(0xFFFFFFFFu, v1, o);
        v2 += __shfl_down_sync(0xFFFFFFFFu, v2, o);
        v3 += __shfl_down_sync(0xFFFFFFFFu, v3, o);
    }
    if ((tid & 31) == 0) {
        int w = tid >> 5;
        sh[w][0] = v0; sh[w][1] = v1; sh[w][2] = v2; sh[w][3] = v3;
    }
    __syncthreads();
    if (tid == 0) {
        double simN = 0.0, disN = 0.0, simC = 0.0, errC = 0.0;
        #pragma unroll
        for (int w = 0; w < 8; w++) {
            simN += sh[w][0]; disN += sh[w][1]; simC += sh[w][2]; errC += sh[w][3];
        }
        double disC = (double)BATCH * N * N - simC;
        double res = errC / (double)BATCH + 0.5 * (simN / simC - disN / disC);
        out[0] = (float)res;
    }
}

extern "C" void kernel_launch(void* const* d_in, const int* in_sizes, int n_in,
                              void* d_out, int out_size)
{
    const float* q   = (const float*)d_in[0];  // [256, 768]
    const float* p   = (const float*)d_in[1];  // [256, 64, 768]
    const int*   lab = (const int*)d_in[2];    // [256, 64]
    (void)in_sizes; (void)n_in; (void)out_size;

    prep_kernel<<<1, 256>>>(lab);
    gram_kernel<<<BATCH, 128>>>(q, p, lab);
    cluster_kernel<<<BATCH, 32>>>(lab);
    finalize_kernel<<<1, 256>>>((float*)d_out);
}

// round 4
// speedup vs baseline: 1.1470x; 1.1470x over previous
#include <cuda_runtime.h>
#include <cstdint>

#define BATCH 256
#define N 64
#define DIM 768
#define CHUNK 64
#define NCHUNK 12
#define DP 68                      // D row pitch (floats)
#define BIGV 1e9f
#define KINF 0xFFFFFFFFFFFFFFFFull

typedef unsigned long long u64;
typedef unsigned int u32;

// Per-batch partials: [sim_num, dis_num, sim_cnt, err_cnt]
__device__ float g_partials[BATCH * 4];

__device__ __forceinline__ u64 u64min(u64 a, u64 b) { return a < b ? a : b; }
__device__ __forceinline__ u64 packkey(float v, int flat) {
    return (((u64)__float_as_uint(v)) << 32) | (unsigned)flat;
}

union F4U { float4 f; u64 u[2]; };

__global__ __launch_bounds__(128) void cluster_kernel(
    const float* __restrict__ q,
    const float* __restrict__ p,
    const int* __restrict__ labels_g)
{
    __shared__ float ST[CHUNK][64];                   // 16 KB, k-major, XOR swizzle
    __shared__ float D[N][DP];                        // 17 KB
    __shared__ u64   rowkey_sm[N];
    __shared__ float sqv[N];
    __shared__ int   lab_in[N];
    __shared__ int   lab_sh[N];
    __shared__ int   s_kmask;
    __shared__ float wred[4][4];

    const int tid = threadIdx.x;
    const int b   = blockIdx.x;
    const float* pb = p + (size_t)b * N * DIM;
    const float* qb = q + (size_t)b * DIM;

    if (tid < N) lab_in[tid] = labels_g[b * N + tid];
    if (tid == 0) s_kmask = 0;
    __syncthreads();
    if (tid < N) atomicOr(&s_kmask, 1 << lab_in[tid]);

    // ---- Gram: G = S S^T, S = q ⊙ P.  128 thr = 16(ti) x 8(tj); tile 4x8 ----
    const int ti = tid >> 3, tj = tid & 7;
    const int i0 = ti * 4, j0 = tj * 8;
    const int kvq  = (tid & 15) * 4;    // k-column offset this thread loads/stores
    const int kqb  = kvq >> 2;          // k-block index for swizzle
    const int prow = tid >> 4;          // base row (+8e)

    u64 acc[4][4];
    #pragma unroll
    for (int r = 0; r < 4; r++)
        #pragma unroll
        for (int cp = 0; cp < 4; cp++) acc[r][cp] = 0ull;

    // prologue: prefetch chunk 0 into registers
    float4 pv[8];
    float4 qv = *reinterpret_cast<const float4*>(qb + kvq);
    #pragma unroll
    for (int e = 0; e < 8; e++)
        pv[e] = *reinterpret_cast<const float4*>(pb + (prow + 8 * e) * DIM + kvq);

    for (int ch = 0; ch < NCHUNK; ch++) {
        __syncthreads();   // previous chunk's readers done
        // store scaled tile (k-major + XOR swizzle)
        #pragma unroll
        for (int e = 0; e < 8; e++) {
            int row = prow + 8 * e;
            int col = (((row >> 2) ^ kqb) << 2) + (row & 3);
            ST[kvq + 0][col] = pv[e].x * qv.x;
            ST[kvq + 1][col] = pv[e].y * qv.y;
            ST[kvq + 2][col] = pv[e].z * qv.z;
            ST[kvq + 3][col] = pv[e].w * qv.w;
        }
        // issue next chunk's loads; they complete during this chunk's compute
        if (ch + 1 < NCHUNK) {
            qv = *reinterpret_cast<const float4*>(qb + (ch + 1) * CHUNK + kvq);
            #pragma unroll
            for (int e = 0; e < 8; e++)
                pv[e] = *reinterpret_cast<const float4*>(
                            pb + (prow + 8 * e) * DIM + (ch + 1) * CHUNK + kvq);
        }
        __syncthreads();

        #pragma unroll
        for (int k4 = 0; k4 < 16; k4++) {
            const int avc  = ((ti ^ k4) << 2);
            const int bvc0 = (((2 * tj)     ^ k4) << 2);
            const int bvc1 = (((2 * tj + 1) ^ k4) << 2);
            #pragma unroll
            for (int t = 0; t < 4; t++) {
                const int kk = k4 * 4 + t;
                float4 av = *reinterpret_cast<const float4*>(&ST[kk][avc]);
                F4U B0, B1;
                B0.f = *reinterpret_cast<const float4*>(&ST[kk][bvc0]);
                B1.f = *reinterpret_cast<const float4*>(&ST[kk][bvc1]);
                u64 a0, a1, a2, a3;
                asm("mov.b64 %0, {%1,%1};" : "=l"(a0) : "f"(av.x));
                asm("mov.b64 %0, {%1,%1};" : "=l"(a1) : "f"(av.y));
                asm("mov.b64 %0, {%1,%1};" : "=l"(a2) : "f"(av.z));
                asm("mov.b64 %0, {%1,%1};" : "=l"(a3) : "f"(av.w));
                #pragma unroll
                for (int cp = 0; cp < 4; cp++) {
                    u64 bq = (cp < 2) ? B0.u[cp] : B1.u[cp - 2];
                    asm("fma.rn.f32x2 %0, %1, %2, %0;" : "+l"(acc[0][cp]) : "l"(a0), "l"(bq));
                    asm("fma.rn.f32x2 %0, %1, %2, %0;" : "+l"(acc[1][cp]) : "l"(a1), "l"(bq));
                    asm("fma.rn.f32x2 %0, %1, %2, %0;" : "+l"(acc[2][cp]) : "l"(a2), "l"(bq));
                    asm("fma.rn.f32x2 %0, %1, %2, %0;" : "+l"(acc[3][cp]) : "l"(a3), "l"(bq));
                }
            }
        }
    }

    // unpack accumulators
    float af[4][8];
    #pragma unroll
    for (int r = 0; r < 4; r++)
        #pragma unroll
        for (int cp = 0; cp < 4; cp++) {
            float lo, hi;
            asm("mov.b64 {%0,%1}, %2;" : "=f"(lo), "=f"(hi) : "l"(acc[r][cp]));
            af[r][2 * cp] = lo; af[r][2 * cp + 1] = hi;
        }

    __syncthreads();
    #pragma unroll
    for (int r = 0; r < 4; r++) {
        int i = i0 + r;
        if (i >= j0 && i < j0 + 8) sqv[i] = af[r][i - j0];
    }
    __syncthreads();

    // ---- distances + similar/dissimilar partial sums ----
    float simN = 0.f, disN = 0.f, simC = 0.f;
    #pragma unroll
    for (int r = 0; r < 4; r++) {
        int i = i0 + r;
        int li = lab_in[i];
        #pragma unroll
        for (int c = 0; c < 8; c++) {
            int j = j0 + c;
            float d2 = sqv[i] + sqv[j] - 2.f * af[r][c];
            float dist = (d2 > 0.f) ? sqrtf(d2) : 0.f;
            D[i][j] = dist;
            if (li == lab_in[j]) { simN += dist; simC += 1.f; }
            else                 { disN += dist; }
        }
    }
    __syncthreads();
    if (tid < N) D[tid][tid] = BIGV;
    __syncthreads();

    // ---- initial row-min keys: 2 threads per row, 32 cols each ----
    {
        int row = tid >> 1, part = tid & 1;
        u64 key = KINF;
        #pragma unroll
        for (int f = 0; f < 8; f++) {
            int c = part * 32 + f * 4;
            float4 v = *reinterpret_cast<const float4*>(&D[row][c]);
            key = u64min(key, packkey(v.x, row * 64 + c + 0));
            key = u64min(key, packkey(v.y, row * 64 + c + 1));
            key = u64min(key, packkey(v.z, row * 64 + c + 2));
            key = u64min(key, packkey(v.w, row * 64 + c + 3));
        }
        key = u64min(key, __shfl_down_sync(0xFFFFFFFFu, key, 1));
        if (part == 0) rowkey_sm[row] = key;
    }
    __syncthreads();

    const int merges = N - __popc(s_kmask);

    // ---- single-linkage: warp 0 only, warp-synchronous, O(n) per merge ----
    if (tid < 32) {
        const int lane = tid;
        const int c0 = 2 * lane, c1 = c0 + 1;
        u64 rk0 = rowkey_sm[c0], rk1 = rowkey_sm[c1];
        u64 pend = KINF;
        u64 act = ~0ull;
        int aprev = -1;
        int lab0 = c0, lab1 = c1;

        for (int m = 0; m < merges; m++) {
            u64 cand = u64min(u64min(rk0, rk1), pend);
            // two-phase redux argmin (tie-break = min flat idx, same as u64 min)
            u32 chi = (u32)(cand >> 32);
            u32 h   = __reduce_min_sync(0xFFFFFFFFu, chi);
            u32 cl  = (chi == h) ? (u32)cand : 0xFFFFFFFFu;
            u32 l   = __reduce_min_sync(0xFFFFFFFFu, cl);
            // warp min of pend (materialize previous merge's row-a rowkey)
            u32 phi = (u32)(pend >> 32);
            u32 ph  = __reduce_min_sync(0xFFFFFFFFu, phi);
            u32 plo = (phi == ph) ? (u32)pend : 0xFFFFFFFFu;
            u32 pl  = __reduce_min_sync(0xFFFFFFFFu, plo);
            if (aprev >= 0 && lane == (aprev >> 1)) {
                u64 pr = (((u64)ph) << 32) | pl;
                if (aprev & 1) rk1 = pr; else rk0 = pr;
            }

            int flat = (int)l;
            int a = flat >> 6, bb = flat & 63;   // a < bb by flat minimality on symmetric keys

            act &= ~(1ull << bb);

            float m0 = fminf(D[a][c0], D[bb][c0]);
            float m1 = fminf(D[a][c1], D[bb][c1]);
            D[a][c0] = m0; D[a][c1] = m1;
            D[c0][a] = m0; D[c1][a] = m1;

            u64 k0 = (((act >> c0) & 1ull) && c0 != a) ? packkey(m0, a * 64 + c0) : KINF;
            u64 k1 = (((act >> c1) & 1ull) && c1 != a) ? packkey(m1, a * 64 + c1) : KINF;
            pend = u64min(k0, k1);
            aprev = a;

            if (c0 == a || c0 == bb) rk0 = KINF;
            else if ((act >> c0) & 1ull) {
                if ((int)(rk0 & 63ull) == bb) rk0 = (rk0 & ~63ull) | (unsigned)a;
                rk0 = u64min(rk0, packkey(m0, c0 * 64 + a));
            }
            if (c1 == a || c1 == bb) rk1 = KINF;
            else if ((act >> c1) & 1ull) {
                if ((int)(rk1 & 63ull) == bb) rk1 = (rk1 & ~63ull) | (unsigned)a;
                rk1 = u64min(rk1, packkey(m1, c1 * 64 + a));
            }

            if (lab0 == bb) lab0 = a;
            if (lab1 == bb) lab1 = a;
            __syncwarp();
        }
        lab_sh[c0] = lab0;
        lab_sh[c1] = lab1;
    }
    __syncthreads();

    // ---- error count over this thread's 4x8 tile ----
    float errC = 0.f;
    #pragma unroll
    for (int r = 0; r < 4; r++) {
        int i = i0 + r;
        int ci = lab_sh[i], li = lab_in[i];
        #pragma unroll
        for (int c = 0; c < 8; c++) {
            int j = j0 + c;
            bool adj = (ci == lab_sh[j]);
            bool tru = (li == lab_in[j]);
            if (adj != tru) errC += 1.f;
        }
    }

    // ---- block reduce (4 warps) ----
    float v0 = simN, v1 = disN, v2 = simC, v3 = errC;
    #pragma unroll
    for (int o = 16; o > 0; o >>= 1) {
        v0 += __shfl_down_sync(0xFFFFFFFFu, v0, o);
        v1 += __shfl_down_sync(0xFFFFFFFFu, v1, o);
        v2 += __shfl_down_sync(0xFFFFFFFFu, v2, o);
        v3 += __shfl_down_sync(0xFFFFFFFFu, v3, o);
    }
    if ((tid & 31) == 0) {
        int w = tid >> 5;
        wred[w][0] = v0; wred[w][1] = v1; wred[w][2] = v2; wred[w][3] = v3;
    }
    __syncthreads();
    if (tid == 0) {
        float a0 = 0.f, a1 = 0.f, a2 = 0.f, a3 = 0.f;
        #pragma unroll
        for (int w = 0; w < 4; w++) {
            a0 += wred[w][0]; a1 += wred[w][1]; a2 += wred[w][2]; a3 += wred[w][3];
        }
        g_partials[b * 4 + 0] = a0;
        g_partials[b * 4 + 1] = a1;
        g_partials[b * 4 + 2] = a2;
        g_partials[b * 4 + 3] = a3;
    }
}

__global__ __launch_bounds__(256) void finalize_kernel(float* __restrict__ out)
{
    __shared__ double sh[8][4];
    const int tid = threadIdx.x;
    double v0 = g_partials[tid * 4 + 0];
    double v1 = g_partials[tid * 4 + 1];
    double v2 = g_partials[tid * 4 + 2];
    double v3 = g_partials[tid * 4 + 3];
    #pragma unroll
    for (int o = 16; o > 0; o >>= 1) {
        v0 += __shfl_down_sync(0xFFFFFFFFu, v0, o);
        v1 += __shfl_down_sync(0xFFFFFFFFu, v1, o);
        v2 += __shfl_down_sync(0xFFFFFFFFu, v2, o);
        v3 += __shfl_down_sync(0xFFFFFFFFu, v3, o);
    }
    if ((tid & 31) == 0) {
        int w = tid >> 5;
        sh[w][0] = v0; sh[w][1] = v1; sh[w][2] = v2; sh[w][3] = v3;
    }
    __syncthreads();
    if (tid == 0) {
        double simN = 0.0, disN = 0.0, simC = 0.0, errC = 0.0;
        #pragma unroll
        for (int w = 0; w < 8; w++) {
            simN += sh[w][0]; disN += sh[w][1]; simC += sh[w][2]; errC += sh[w][3];
        }
        double disC = (double)BATCH * N * N - simC;
        double res = errC / (double)BATCH + 0.5 * (simN / simC - disN / disC);
        out[0] = (float)res;
    }
}

extern "C" void kernel_launch(void* const* d_in, const int* in_sizes, int n_in,
                              void* d_out, int out_size)
{
    const float* q   = (const float*)d_in[0];  // [256, 768]
    const float* p   = (const float*)d_in[1];  // [256, 64, 768]
    const int*   lab = (const int*)d_in[2];    // [256, 64]
    (void)in_sizes; (void)n_in; (void)out_size;

    cluster_kernel<<<BATCH, 128>>>(q, p, lab);
    finalize_kernel<<<1, 256>>>((float*)d_out);
}

// round 6
// speedup vs baseline: 1.7278x; 1.5064x over previous
#include <cuda_runtime.h>
#include <cstdint>

#define BATCH 256
#define N 64
#define DIM 768
#define KC 32
#define NCH 24
#define DP 68
#define LP 66
#define BIGV 1e9f
#define KINF 0xFFFFFFFFFFFFFFFFull

typedef unsigned long long u64;
typedef unsigned int u32;

__device__ float g_partials[BATCH * 4];

__device__ __forceinline__ u64 u64min(u64 a, u64 b) { return a < b ? a : b; }
__device__ __forceinline__ u64 packkey(float v, int flat) {
    return (((u64)__float_as_uint(v)) << 32) | (unsigned)flat;
}
__device__ __forceinline__ u32 to_tf32(float x) {
    u32 r; asm("cvt.rna.tf32.f32 %0, %1;" : "=r"(r) : "f"(x)); return r;
}
__device__ __forceinline__ void mma_tf32(float* d, const u32* a, const u32* b) {
    asm volatile("mma.sync.aligned.m16n8k8.row.col.f32.tf32.tf32.f32 "
        "{%0,%1,%2,%3}, {%4,%5,%6,%7}, {%8,%9}, {%0,%1,%2,%3};"
        : "+f"(d[0]), "+f"(d[1]), "+f"(d[2]), "+f"(d[3])
        : "r"(a[0]), "r"(a[1]), "r"(a[2]), "r"(a[3]), "r"(b[0]), "r"(b[1]));
}

__global__ __launch_bounds__(128, 2) void cluster_kernel(
    const float* __restrict__ q,
    const float* __restrict__ p,
    const int* __restrict__ labels_g)
{
    // FRAG: AF[0..4095] (A frags: [ks4][mt8][reg4][lane32]),
    //       BF[4096..6143] ([ks4][nt8][reg2][lane32]); reused as Lsm[64][66] after GEMM
    __shared__ __align__(16) u32   FRAG[6144];     // 24 KB
    __shared__ __align__(16) float D[N][DP];       // 17 KB (T during GEMM epilogue, then distances)
    __shared__ __align__(16) float qs[DIM];        // 3 KB
    __shared__ u64   rowkey_sm[N];
    __shared__ float sqv[N];
    __shared__ int   lab_in[N];
    __shared__ int   lab_sh[N];
    __shared__ int   s_kmask;
    __shared__ float wred[4][4];

    const int tid  = threadIdx.x;
    const int wid  = tid >> 5;
    const int lane = tid & 31;
    const int b    = blockIdx.x;
    const float* pb = p + (size_t)b * N * DIM;
    const float* qb = q + (size_t)b * DIM;

    for (int k = tid; k < DIM; k += 128) qs[k] = qb[k];
    if (tid < N) lab_in[tid] = labels_g[b * N + tid];
    if (tid == 0) s_kmask = 0;
    __syncthreads();
    if (tid < N) atomicOr(&s_kmask, 1 << lab_in[tid]);

    // per-thread producer mapping: 4 (row, kcf) pairs, invariant across chunks
    int rowE[4], kcfE[4], offAH[4], offAL[4], offB[4];
    #pragma unroll
    for (int e = 0; e < 4; e++) {
        int idx4 = tid + 128 * e;
        int row  = idx4 >> 3;            // 0..63
        int kcf  = (idx4 & 7) * 4;       // 0,4,...,28
        rowE[e] = row; kcfE[e] = kcf;
        int ks    = kcf >> 3;            // kstep 0..3
        int kcbit = (kcf >> 2) & 1;
        int r     = row & 15;
        int hbit  = (r >> 3) & 1;
        int mtH   = row >> 4;            // 0..3
        int regA  = kcbit * 2 + hbit;
        int lane4 = (r & 7) * 4;
        int rot   = (ks * 2 + kcbit) * 4;
        int phys  = (lane4 + rot) & 31;
        int segH  = ks * 32 + mtH * 4 + regA;
        offAH[e]  = segH * 32 + phys;
        offAL[e]  = (segH + 16) * 32 + phys;        // mtile + 4
        int segB  = ks * 16 + (row >> 3) * 2 + kcbit;
        offB[e]   = 4096 + segB * 32 + phys;
    }

    float dacc[2][8][4];
    #pragma unroll
    for (int ms = 0; ms < 2; ms++)
        #pragma unroll
        for (int nt = 0; nt < 8; nt++)
            #pragma unroll
            for (int c = 0; c < 4; c++) dacc[ms][nt][c] = 0.f;

    // prologue: prefetch chunk 0
    float4 pv[4];
    #pragma unroll
    for (int e = 0; e < 4; e++)
        pv[e] = *reinterpret_cast<const float4*>(pb + rowE[e] * DIM + kcfE[e]);

    #pragma unroll 1
    for (int ch = 0; ch < NCH; ch++) {
        __syncthreads();   // previous chunk's fragment readers done
        #pragma unroll
        for (int e = 0; e < 4; e++) {
            const float4 qv = *reinterpret_cast<const float4*>(&qs[ch * KC + kcfE[e]]);
            float sx = pv[e].x * qv.x, sy = pv[e].y * qv.y,
                  sz = pv[e].z * qv.z, sw = pv[e].w * qv.w;
            u32 hx = to_tf32(sx), hy = to_tf32(sy), hz = to_tf32(sz), hw = to_tf32(sw);
            float fx = sx - __uint_as_float(hx), fy = sy - __uint_as_float(hy);
            float fz = sz - __uint_as_float(hz), fw = sw - __uint_as_float(hw);
            u32 lx = to_tf32(fx), ly = to_tf32(fy), lz = to_tf32(fz), lw = to_tf32(fw);
            *reinterpret_cast<uint4*>(&FRAG[offAH[e]]) = make_uint4(hx, hy, hz, hw);
            *reinterpret_cast<uint4*>(&FRAG[offAL[e]]) = make_uint4(lx, ly, lz, lw);
            *reinterpret_cast<uint4*>(&FRAG[offB[e]])  = make_uint4(hx, hy, hz, hw);
        }
        if (ch + 1 < NCH) {
            #pragma unroll
            for (int e = 0; e < 4; e++)
                pv[e] = *reinterpret_cast<const float4*>(
                            pb + rowE[e] * DIM + (ch + 1) * KC + kcfE[e]);
        }
        __syncthreads();

        #pragma unroll
        for (int ks = 0; ks < 4; ks++) {
            u32 afr[2][4];
            #pragma unroll
            for (int ms = 0; ms < 2; ms++) {
                int mt = wid + ms * 4;
                #pragma unroll
                for (int rg = 0; rg < 4; rg++) {
                    int seg = ks * 32 + mt * 4 + rg;
                    int rot = (ks * 2 + (rg >> 1)) * 4;
                    afr[ms][rg] = FRAG[seg * 32 + ((lane + rot) & 31)];
                }
            }
            #pragma unroll
            for (int nt = 0; nt < 8; nt++) {
                u32 bfr[2];
                #pragma unroll
                for (int rg = 0; rg < 2; rg++) {
                    int seg = ks * 16 + nt * 2 + rg;
                    int rot = (ks * 2 + rg) * 4;
                    bfr[rg] = FRAG[4096 + seg * 32 + ((lane + rot) & 31)];
                }
                mma_tf32(dacc[0][nt], afr[0], bfr);
                mma_tf32(dacc[1][nt], afr[1], bfr);
            }
        }
    }

    __syncthreads();   // all frag reads done: FRAG becomes Lsm
    float* Lsm = reinterpret_cast<float*>(FRAG);

    // C writeout: T (hi tiles, mt = wid) -> D rows 16w..; L (lo, mt = wid+4) -> Lsm
    {
        int rb = lane >> 2;
        int cb = (lane & 3) * 2;
        #pragma unroll
        for (int nt = 0; nt < 8; nt++) {
            int col = nt * 8 + cb;
            int r0 = 16 * wid + rb;
            D[r0][col]       = dacc[0][nt][0];
            D[r0][col + 1]   = dacc[0][nt][1];
            D[r0 + 8][col]     = dacc[0][nt][2];
            D[r0 + 8][col + 1] = dacc[0][nt][3];
            Lsm[r0 * LP + col]           = dacc[1][nt][0];
            Lsm[r0 * LP + col + 1]       = dacc[1][nt][1];
            Lsm[(r0 + 8) * LP + col]     = dacc[1][nt][2];
            Lsm[(r0 + 8) * LP + col + 1] = dacc[1][nt][3];
        }
    }
    __syncthreads();

    if (tid < N)
        sqv[tid] = (D[tid][tid] + Lsm[tid * LP + tid]) + Lsm[tid * LP + tid];
    __syncthreads();

    // ---- distances + sim/dis partials (upper triangle, mirrored) ----
    float simN = 0.f, disN = 0.f, simC = 0.f;
    for (int e = tid; e < 4096; e += 128) {
        int i = e >> 6, j = e & 63;
        if (i > j) continue;
        if (i == j) { simC += 1.f; D[i][i] = BIGV; continue; }
        float g = (D[i][j] + Lsm[i * LP + j]) + Lsm[j * LP + i];
        float d2 = sqv[i] + sqv[j] - 2.f * g;
        float dist = (d2 > 0.f) ? sqrtf(d2) : 0.f;
        D[i][j] = dist; D[j][i] = dist;
        if (lab_in[i] == lab_in[j]) { simN += 2.f * dist; simC += 2.f; }
        else                        { disN += 2.f * dist; }
    }
    __syncthreads();

    // ---- initial row-min keys: 2 threads per row ----
    {
        int row = tid >> 1, part = tid & 1;
        u64 key = KINF;
        #pragma unroll
        for (int f = 0; f < 8; f++) {
            int c = part * 32 + f * 4;
            float4 v = *reinterpret_cast<const float4*>(&D[row][c]);
            key = u64min(key, packkey(v.x, row * 64 + c + 0));
            key = u64min(key, packkey(v.y, row * 64 + c + 1));
            key = u64min(key, packkey(v.z, row * 64 + c + 2));
            key = u64min(key, packkey(v.w, row * 64 + c + 3));
        }
        key = u64min(key, __shfl_down_sync(0xFFFFFFFFu, key, 1));
        if (part == 0) rowkey_sm[row] = key;
    }
    __syncthreads();

    const int merges = N - __popc(s_kmask);

    // ---- single-linkage: warp 0, O(n) per merge (validated R4 path) ----
    if (tid < 32) {
        const int c0 = 2 * lane, c1 = c0 + 1;
        u64 rk0 = rowkey_sm[c0], rk1 = rowkey_sm[c1];
        u64 pend = KINF;
        u64 act = ~0ull;
        int aprev = -1;
        int lab0 = c0, lab1 = c1;

        for (int m = 0; m < merges; m++) {
            u64 cand = u64min(u64min(rk0, rk1), pend);
            u32 chi = (u32)(cand >> 32);
            u32 h   = __reduce_min_sync(0xFFFFFFFFu, chi);
            u32 cl  = (chi == h) ? (u32)cand : 0xFFFFFFFFu;
            u32 l   = __reduce_min_sync(0xFFFFFFFFu, cl);
            u32 phi = (u32)(pend >> 32);
            u32 ph  = __reduce_min_sync(0xFFFFFFFFu, phi);
            u32 plo = (phi == ph) ? (u32)pend : 0xFFFFFFFFu;
            u32 pl  = __reduce_min_sync(0xFFFFFFFFu, plo);
            if (aprev >= 0 && lane == (aprev >> 1)) {
                u64 pr = (((u64)ph) << 32) | pl;
                if (aprev & 1) rk1 = pr; else rk0 = pr;
            }

            int flat = (int)l;
            int a = flat >> 6, bb = flat & 63;

            act &= ~(1ull << bb);

            float m0 = fminf(D[a][c0], D[bb][c0]);
            float m1 = fminf(D[a][c1], D[bb][c1]);
            D[a][c0] = m0; D[a][c1] = m1;
            D[c0][a] = m0; D[c1][a] = m1;

            u64 k0 = (((act >> c0) & 1ull) && c0 != a) ? packkey(m0, a * 64 + c0) : KINF;
            u64 k1 = (((act >> c1) & 1ull) && c1 != a) ? packkey(m1, a * 64 + c1) : KINF;
            pend = u64min(k0, k1);
            aprev = a;

            if (c0 == a || c0 == bb) rk0 = KINF;
            else if ((act >> c0) & 1ull) {
                if ((int)(rk0 & 63ull) == bb) rk0 = (rk0 & ~63ull) | (unsigned)a;
                rk0 = u64min(rk0, packkey(m0, c0 * 64 + a));
            }
            if (c1 == a || c1 == bb) rk1 = KINF;
            else if ((act >> c1) & 1ull) {
                if ((int)(rk1 & 63ull) == bb) rk1 = (rk1 & ~63ull) | (unsigned)a;
                rk1 = u64min(rk1, packkey(m1, c1 * 64 + a));
            }

            if (lab0 == bb) lab0 = a;
            if (lab1 == bb) lab1 = a;
            __syncwarp();
        }
        lab_sh[c0] = lab0;
        lab_sh[c1] = lab1;
    }
    __syncthreads();

    // ---- error count ----
    float errC = 0.f;
    for (int e = tid; e < 4096; e += 128) {
        int i = e >> 6, j = e & 63;
        bool adj = (lab_sh[i] == lab_sh[j]);
        bool tru = (lab_in[i] == lab_in[j]);
        if (adj != tru) errC += 1.f;
    }

    float v0 = simN, v1 = disN, v2 = simC, v3 = errC;
    #pragma unroll
    for (int o = 16; o > 0; o >>= 1) {
        v0 += __shfl_down_sync(0xFFFFFFFFu, v0, o);
        v1 += __shfl_down_sync(0xFFFFFFFFu, v1, o);
        v2 += __shfl_down_sync(0xFFFFFFFFu, v2, o);
        v3 += __shfl_down_sync(0xFFFFFFFFu, v3, o);
    }
    if (lane == 0) {
        wred[wid][0] = v0; wred[wid][1] = v1; wred[wid][2] = v2; wred[wid][3] = v3;
    }
    __syncthreads();
    if (tid == 0) {
        float a0 = 0.f, a1 = 0.f, a2 = 0.f, a3 = 0.f;
        #pragma unroll
        for (int w = 0; w < 4; w++) {
            a0 += wred[w][0]; a1 += wred[w][1]; a2 += wred[w][2]; a3 += wred[w][3];
        }
        g_partials[b * 4 + 0] = a0;
        g_partials[b * 4 + 1] = a1;
        g_partials[b * 4 + 2] = a2;
        g_partials[b * 4 + 3] = a3;
    }
}

__global__ __launch_bounds__(256) void finalize_kernel(float* __restrict__ out)
{
    __shared__ double sh[8][4];
    const int tid = threadIdx.x;
    double v0 = g_partials[tid * 4 + 0];
    double v1 = g_partials[tid * 4 + 1];
    double v2 = g_partials[tid * 4 + 2];
    double v3 = g_partials[tid * 4 + 3];
    #pragma unroll
    for (int o = 16; o > 0; o >>= 1) {
        v0 += __shfl_down_sync(0xFFFFFFFFu, v0, o);
        v1 += __shfl_down_sync(0xFFFFFFFFu, v1, o);
        v2 += __shfl_down_sync(0xFFFFFFFFu, v2, o);
        v3 += __shfl_down_sync(0xFFFFFFFFu, v3, o);
    }
    if ((tid & 31) == 0) {
        int w = tid >> 5;
        sh[w][0] = v0; sh[w][1] = v1; sh[w][2] = v2; sh[w][3] = v3;
    }
    __syncthreads();
    if (tid == 0) {
        double simN = 0.0, disN = 0.0, simC = 0.0, errC = 0.0;
        #pragma unroll
        for (int w = 0; w < 8; w++) {
            simN += sh[w][0]; disN += sh[w][1]; simC += sh[w][2]; errC += sh[w][3];
        }
        double disC = (double)BATCH * N * N - simC;
        double res = errC / (double)BATCH + 0.5 * (simN / simC - disN / disC);
        out[0] = (float)res;
    }
}

extern "C" void kernel_launch(void* const* d_in, const int* in_sizes, int n_in,
                              void* d_out, int out_size)
{
    const float* q   = (const float*)d_in[0];
    const float* p   = (const float*)d_in[1];
    const int*   lab = (const int*)d_in[2];
    (void)in_sizes; (void)n_in; (void)out_size;

    cluster_kernel<<<BATCH, 128>>>(q, p, lab);
    finalize_kernel<<<1, 256>>>((float*)d_out);
}